// round 9
// baseline (speedup 1.0000x reference)
#include <cuda_runtime.h>
#include <cuda_fp16.h>
#include <mma.h>

using namespace nvcuda;

// ---------------------------------------------------------------------------
// EdgeDecoder: out[e] = relu([zu[row]; zr[col]] @ W1 + b1) @ W2 + b2
// Restructured: U = zu @ W1_top + b1 ; R = zr @ W1_bot  (fp16 HMMA, fp32 acc)
// U,R stored fp16. R9: counting-sort edges by row (NBINS now covers the full
// z_user row range -- R8's guard compared against the array size and always
// fell back). Sorted edges make U gathers L1-resident; R stays random.
// ---------------------------------------------------------------------------

#define HDIM 128
#define MAX_USER   100000
#define MAX_RECIPE 50000
#define MAX_E      (1 << 20)          // 1,048,576 >= 1e6
#define NBINS      100352             // 1024 * 98 >= MAX_USER
#define SCAN_CHUNK 98

__device__ __half g_U[(size_t)MAX_USER * HDIM];    // 25.6 MB
__device__ __half g_R[(size_t)MAX_RECIPE * HDIM];  // 12.8 MB
__device__ int    g_is64;
__device__ int    g_hist[NBINS];
__device__ int    g_offs[NBINS];
__device__ unsigned long long g_sorted[MAX_E];     // row:22 | col:22 | eid:20

#define APITCH 136
#define TILEB  (128 * APITCH * 2)
#define CPITCH 132

// ---------------------------------------------------------------------------
// Phase 1: fp16 HMMA precompute (unchanged). Also sets g_is64.
// ---------------------------------------------------------------------------
__global__ __launch_bounds__(512, 2)
void precompute_kernel(const float* __restrict__ Zu,
                       const float* __restrict__ Zr,
                       const float* __restrict__ W1,
                       const float* __restrict__ b1,
                       const unsigned long long* __restrict__ eidx,
                       int gu, int Mu, int Mr)
{
    extern __shared__ __align__(16) char sm[];
    __half* Ah = (__half*)sm;
    __half* Bh = (__half*)(sm + TILEB);

    if (blockIdx.x == 0 && threadIdx.x == 0) {
        int is64 = 1;
        #pragma unroll
        for (int i = 0; i < 32; ++i)
            if ((eidx[i] >> 32) != 0ull) is64 = 0;
        g_is64 = is64;
    }

    const bool isR = (blockIdx.x >= (unsigned)gu);
    const int  blk = isR ? (blockIdx.x - gu) : blockIdx.x;
    const int  M   = isR ? Mr : Mu;
    const float* __restrict__ Z  = isR ? Zr : Zu;
    const float* __restrict__ Wp = isR ? (W1 + HDIM * HDIM) : W1;
    __half* __restrict__ C       = isR ? g_R : g_U;

    const int tid  = threadIdx.x;
    const int row0 = blk * 128;

    #pragma unroll
    for (int idx = tid; idx < 4096; idx += 512) {
        const int r  = idx >> 5;
        const int c4 = (idx & 31) * 4;
        float4 v = ((const float4*)Wp)[idx];
        __half2 p0 = __float22half2_rn(make_float2(v.x, v.y));
        __half2 p1 = __float22half2_rn(make_float2(v.z, v.w));
        uint2 hh; hh.x = *(unsigned*)&p0; hh.y = *(unsigned*)&p1;
        *(uint2*)&Bh[r * APITCH + c4] = hh;
    }
    #pragma unroll
    for (int idx = tid; idx < 4096; idx += 512) {
        const int r  = idx >> 5;
        const int c4 = (idx & 31) * 4;
        const int gr = row0 + r;
        float4 v = make_float4(0.f, 0.f, 0.f, 0.f);
        if (gr < M) v = ((const float4*)Z)[(size_t)gr * 32 + (idx & 31)];
        __half2 p0 = __float22half2_rn(make_float2(v.x, v.y));
        __half2 p1 = __float22half2_rn(make_float2(v.z, v.w));
        uint2 hh; hh.x = *(unsigned*)&p0; hh.y = *(unsigned*)&p1;
        *(uint2*)&Ah[r * APITCH + c4] = hh;
    }
    __syncthreads();

    const int warp = tid >> 5;
    const int wm   = warp >> 1;
    const int wn   = warp & 1;

    wmma::fragment<wmma::accumulator, 16, 16, 16, float> acc[4];
    #pragma unroll
    for (int j = 0; j < 4; ++j) wmma::fill_fragment(acc[j], 0.f);

    wmma::fragment<wmma::matrix_a, 16, 16, 16, __half, wmma::row_major> fA;
    wmma::fragment<wmma::matrix_b, 16, 16, 16, __half, wmma::row_major> fB;

    #pragma unroll
    for (int k = 0; k < HDIM; k += 16) {
        wmma::load_matrix_sync(fA, Ah + (wm * 16) * APITCH + k, APITCH);
        #pragma unroll
        for (int j = 0; j < 4; ++j) {
            wmma::load_matrix_sync(fB, Bh + k * APITCH + wn * 64 + j * 16, APITCH);
            wmma::mma_sync(acc[j], fA, fB, acc[j]);
        }
    }

    __syncthreads();
    float* Cf = (float*)sm;
    #pragma unroll
    for (int j = 0; j < 4; ++j)
        wmma::store_matrix_sync(Cf + (wm * 16) * CPITCH + wn * 64 + j * 16,
                                acc[j], CPITCH, wmma::mem_row_major);
    __syncthreads();

    #pragma unroll
    for (int idx = tid; idx < 4096; idx += 512) {
        const int r  = idx >> 5;
        const int c4 = (idx & 31) * 4;
        const int gr = row0 + r;
        if (gr < M) {
            float4 v = *(const float4*)&Cf[r * CPITCH + c4];
            if (!isR) {
                const float4 bv = *(const float4*)&b1[c4];
                v.x += bv.x; v.y += bv.y; v.z += bv.z; v.w += bv.w;
            }
            __half2 h0 = __float22half2_rn(make_float2(v.x, v.y));
            __half2 h1 = __float22half2_rn(make_float2(v.z, v.w));
            uint2 o; o.x = *(unsigned*)&h0; o.y = *(unsigned*)&h1;
            *(uint2*)&C[(size_t)gr * HDIM + c4] = o;
        }
    }
}

// ---------------------------------------------------------------------------
// Counting sort of edges by row.
// ---------------------------------------------------------------------------
__device__ __forceinline__ void load_idx(const void* eidx, int is64, int e,
                                         int E, int& row, int& col)
{
    if (is64) {
        const long long* p = (const long long*)eidx;
        row = (int)p[e];
        col = (int)p[(size_t)E + e];
    } else {
        const int* p = (const int*)eidx;
        row = p[e];
        col = p[(size_t)E + e];
    }
}

__global__ void zero_hist_kernel() {
    int i = blockIdx.x * blockDim.x + threadIdx.x;
    if (i < NBINS) g_hist[i] = 0;
}

__global__ void hist_kernel(const void* __restrict__ eidx, int E) {
    const int is64 = g_is64;
    for (int e = blockIdx.x * blockDim.x + threadIdx.x; e < E;
         e += gridDim.x * blockDim.x) {
        int row, col;
        load_idx(eidx, is64, e, E, row, col);
        atomicAdd(&g_hist[row], 1);
    }
}

__global__ __launch_bounds__(1024, 1)
void scan_kernel() {
    __shared__ int part[1024];
    const int t    = threadIdx.x;
    const int base = t * SCAN_CHUNK;

    int s = 0;
    #pragma unroll
    for (int i = 0; i < SCAN_CHUNK; ++i) s += g_hist[base + i];
    part[t] = s;
    __syncthreads();

    for (int off = 1; off < 1024; off <<= 1) {
        int v = (t >= off) ? part[t - off] : 0;
        __syncthreads();
        part[t] += v;
        __syncthreads();
    }

    int run = part[t] - s;
    #pragma unroll
    for (int i = 0; i < SCAN_CHUNK; ++i) {
        int h = g_hist[base + i];
        g_offs[base + i] = run;
        run += h;
    }
}

__global__ void scatter_kernel(const void* __restrict__ eidx, int E) {
    const int is64 = g_is64;
    for (int e = blockIdx.x * blockDim.x + threadIdx.x; e < E;
         e += gridDim.x * blockDim.x) {
        int row, col;
        load_idx(eidx, is64, e, E, row, col);
        int pos = atomicAdd(&g_offs[row], 1);
        g_sorted[pos] = ((unsigned long long)row << 42)
                      | ((unsigned long long)col << 20)
                      | (unsigned)e;
    }
}

// ---------------------------------------------------------------------------
// Phase 2 (sorted): 4 edges/warp (8 lanes each) over the row-sorted list.
// ---------------------------------------------------------------------------
__device__ __forceinline__ float dot8h(uint4 u, uint4 r, float4 w0, float4 w1) {
    const __half2 z2 = __float2half2_rn(0.f);
    __half2 a0 = __hmax2(__hadd2(*(__half2*)&u.x, *(__half2*)&r.x), z2);
    __half2 a1 = __hmax2(__hadd2(*(__half2*)&u.y, *(__half2*)&r.y), z2);
    __half2 a2 = __hmax2(__hadd2(*(__half2*)&u.z, *(__half2*)&r.z), z2);
    __half2 a3 = __hmax2(__hadd2(*(__half2*)&u.w, *(__half2*)&r.w), z2);
    float2 f0 = __half22float2(a0);
    float2 f1 = __half22float2(a1);
    float2 f2 = __half22float2(a2);
    float2 f3 = __half22float2(a3);
    float s;
    s  = f0.x * w0.x;
    s  = fmaf(f0.y, w0.y, s);
    s  = fmaf(f1.x, w0.z, s);
    s  = fmaf(f1.y, w0.w, s);
    s  = fmaf(f2.x, w1.x, s);
    s  = fmaf(f2.y, w1.y, s);
    s  = fmaf(f3.x, w1.z, s);
    s  = fmaf(f3.y, w1.w, s);
    return s;
}

__global__ __launch_bounds__(256)
void edge_sorted_kernel(const float* __restrict__ W2,
                        const float* __restrict__ b2,
                        float* __restrict__ out,
                        int E)
{
    __shared__ float w2s[HDIM];
    const int tid = threadIdx.x;
    if (tid < HDIM) w2s[tid] = W2[tid];
    __syncthreads();

    const int warp = (blockIdx.x * 256 + tid) >> 5;
    const int lane = tid & 31;
    const int sub  = lane >> 3;
    const int l8   = lane & 7;
    const int i    = warp * 4 + sub;
    if (i >= E) return;

    const unsigned long long pk = g_sorted[i];
    const int row = (int)(pk >> 42);
    const int col = (int)((pk >> 20) & 0x3FFFFF);
    const int eid = (int)(pk & 0xFFFFF);

    const uint4* Up = (const uint4*)&g_U[(size_t)row * HDIM];
    const uint4* Rp = (const uint4*)&g_R[(size_t)col * HDIM];
    const uint4 ua = Up[l8],  ub = Up[l8 + 8];
    const uint4 ra = Rp[l8],  rb = Rp[l8 + 8];

    const float4* w4 = (const float4*)w2s;
    const float4 w0 = w4[2 * l8],      w1 = w4[2 * l8 + 1];
    const float4 w2 = w4[16 + 2 * l8], w3 = w4[16 + 2 * l8 + 1];

    float s = dot8h(ua, ra, w0, w1) + dot8h(ub, rb, w2, w3);

    const unsigned mask = 0xFFu << (sub * 8);
    #pragma unroll
    for (int off = 4; off; off >>= 1)
        s += __shfl_xor_sync(mask, s, off);

    if (l8 == 0) out[eid] = s + __ldg(b2);
}

// Fallback (unsorted) for out-of-range shapes.
__global__ __launch_bounds__(256)
void edge_kernel(const void* __restrict__ eidx,
                 const float* __restrict__ W2,
                 const float* __restrict__ b2,
                 float* __restrict__ out,
                 int E)
{
    __shared__ float w2s[HDIM];
    const int tid = threadIdx.x;
    if (tid < HDIM) w2s[tid] = W2[tid];
    __syncthreads();

    const int warp = (blockIdx.x * 256 + tid) >> 5;
    const int lane = tid & 31;
    const int sub  = lane >> 3;
    const int l8   = lane & 7;
    const int e    = warp * 4 + sub;
    if (e >= E) return;

    int row, col;
    load_idx(eidx, g_is64, e, E, row, col);

    const uint4* Up = (const uint4*)&g_U[(size_t)row * HDIM];
    const uint4* Rp = (const uint4*)&g_R[(size_t)col * HDIM];
    const uint4 ua = Up[l8],  ub = Up[l8 + 8];
    const uint4 ra = Rp[l8],  rb = Rp[l8 + 8];

    const float4* w4 = (const float4*)w2s;
    const float4 w0 = w4[2 * l8],      w1 = w4[2 * l8 + 1];
    const float4 w2 = w4[16 + 2 * l8], w3 = w4[16 + 2 * l8 + 1];

    float s = dot8h(ua, ra, w0, w1) + dot8h(ub, rb, w2, w3);

    const unsigned mask = 0xFFu << (sub * 8);
    #pragma unroll
    for (int off = 4; off; off >>= 1)
        s += __shfl_xor_sync(mask, s, off);

    if (l8 == 0) out[e] = s + __ldg(b2);
}

// ---------------------------------------------------------------------------
extern "C" void kernel_launch(void* const* d_in, const int* in_sizes, int n_in,
                              void* d_out, int out_size)
{
    const float* z_user   = (const float*)d_in[0];
    const float* z_recipe = (const float*)d_in[1];
    const void*  eidx     = d_in[2];
    const float* W1       = (const float*)d_in[3];
    const float* b1       = (const float*)d_in[4];
    const float* W2       = (const float*)d_in[5];
    const float* b2       = (const float*)d_in[6];
    float* out = (float*)d_out;

    const int Mu = in_sizes[0] / HDIM;
    const int Mr = in_sizes[1] / HDIM;
    const int E  = in_sizes[2] / 2;

    const int SMEM = 2 * TILEB;
    cudaFuncSetAttribute(precompute_kernel,
                         cudaFuncAttributeMaxDynamicSharedMemorySize, SMEM);

    const int gu = (Mu + 127) / 128;
    const int gr = (Mr + 127) / 128;
    precompute_kernel<<<gu + gr, 512, SMEM>>>(z_user, z_recipe, W1, b1,
                                              (const unsigned long long*)eidx,
                                              gu, Mu, Mr);

    // Sorted path valid when row values (bounded by Mu, the z_user row count)
    // fit the histogram, and row/col/eid fit the 22/22/20-bit packing.
    const bool sortable = (E <= MAX_E) && (Mu <= NBINS) &&
                          (Mu < (1 << 22)) && (Mr < (1 << 22));
    if (sortable) {
        zero_hist_kernel<<<(NBINS + 255) / 256, 256>>>();
        hist_kernel<<<1024, 256>>>(eidx, E);
        scan_kernel<<<1, 1024>>>();
        scatter_kernel<<<1024, 256>>>(eidx, E);
        edge_sorted_kernel<<<(E + 31) / 32, 256>>>(W2, b2, out, E);
    } else {
        edge_kernel<<<(E + 31) / 32, 256>>>(eidx, W2, b2, out, E);
    }
}

// round 10
// speedup vs baseline: 1.6807x; 1.6807x over previous
#include <cuda_runtime.h>
#include <cuda_fp16.h>
#include <mma.h>

using namespace nvcuda;

// ---------------------------------------------------------------------------
// EdgeDecoder: out[e] = relu([zu[row]; zr[col]] @ W1 + b1) @ W2 + b2
// Restructured: U = zu @ W1_top + b1 ; R = zr @ W1_bot  (fp16 HMMA, fp32 acc)
// U,R stored fp16. Counting-sort edges by row -> U gathers L1-resident.
// R10: scan rebuilt as 3 coalesced stages (R9's single-block strided scan
//      was 98.6us of single-SM uncoalesced wavefronts).
// ---------------------------------------------------------------------------

#define HDIM 128
#define MAX_USER   100000
#define MAX_RECIPE 50000
#define MAX_E      (1 << 20)
#define NBLK_SCAN  392
#define NBINS      (NBLK_SCAN * 256)   // 100352 >= MAX_USER

__device__ __half g_U[(size_t)MAX_USER * HDIM];
__device__ __half g_R[(size_t)MAX_RECIPE * HDIM];
__device__ int    g_is64;
__device__ int    g_hist[NBINS];
__device__ int    g_offs[NBINS];
__device__ int    g_bsum[NBLK_SCAN];
__device__ int    g_bpre[NBLK_SCAN];
__device__ unsigned long long g_sorted[MAX_E];   // row:22 | col:22 | eid:20

#define APITCH 136
#define TILEB  (128 * APITCH * 2)
#define CPITCH 132

// ---------------------------------------------------------------------------
// Phase 1: fp16 HMMA precompute (unchanged). Also sets g_is64.
// ---------------------------------------------------------------------------
__global__ __launch_bounds__(512, 2)
void precompute_kernel(const float* __restrict__ Zu,
                       const float* __restrict__ Zr,
                       const float* __restrict__ W1,
                       const float* __restrict__ b1,
                       const unsigned long long* __restrict__ eidx,
                       int gu, int Mu, int Mr)
{
    extern __shared__ __align__(16) char sm[];
    __half* Ah = (__half*)sm;
    __half* Bh = (__half*)(sm + TILEB);

    if (blockIdx.x == 0 && threadIdx.x == 0) {
        int is64 = 1;
        #pragma unroll
        for (int i = 0; i < 32; ++i)
            if ((eidx[i] >> 32) != 0ull) is64 = 0;
        g_is64 = is64;
    }

    const bool isR = (blockIdx.x >= (unsigned)gu);
    const int  blk = isR ? (blockIdx.x - gu) : blockIdx.x;
    const int  M   = isR ? Mr : Mu;
    const float* __restrict__ Z  = isR ? Zr : Zu;
    const float* __restrict__ Wp = isR ? (W1 + HDIM * HDIM) : W1;
    __half* __restrict__ C       = isR ? g_R : g_U;

    const int tid  = threadIdx.x;
    const int row0 = blk * 128;

    #pragma unroll
    for (int idx = tid; idx < 4096; idx += 512) {
        const int r  = idx >> 5;
        const int c4 = (idx & 31) * 4;
        float4 v = ((const float4*)Wp)[idx];
        __half2 p0 = __float22half2_rn(make_float2(v.x, v.y));
        __half2 p1 = __float22half2_rn(make_float2(v.z, v.w));
        uint2 hh; hh.x = *(unsigned*)&p0; hh.y = *(unsigned*)&p1;
        *(uint2*)&Bh[r * APITCH + c4] = hh;
    }
    #pragma unroll
    for (int idx = tid; idx < 4096; idx += 512) {
        const int r  = idx >> 5;
        const int c4 = (idx & 31) * 4;
        const int gr = row0 + r;
        float4 v = make_float4(0.f, 0.f, 0.f, 0.f);
        if (gr < M) v = ((const float4*)Z)[(size_t)gr * 32 + (idx & 31)];
        __half2 p0 = __float22half2_rn(make_float2(v.x, v.y));
        __half2 p1 = __float22half2_rn(make_float2(v.z, v.w));
        uint2 hh; hh.x = *(unsigned*)&p0; hh.y = *(unsigned*)&p1;
        *(uint2*)&Ah[r * APITCH + c4] = hh;
    }
    __syncthreads();

    const int warp = tid >> 5;
    const int wm   = warp >> 1;
    const int wn   = warp & 1;

    wmma::fragment<wmma::accumulator, 16, 16, 16, float> acc[4];
    #pragma unroll
    for (int j = 0; j < 4; ++j) wmma::fill_fragment(acc[j], 0.f);

    wmma::fragment<wmma::matrix_a, 16, 16, 16, __half, wmma::row_major> fA;
    wmma::fragment<wmma::matrix_b, 16, 16, 16, __half, wmma::row_major> fB;

    #pragma unroll
    for (int k = 0; k < HDIM; k += 16) {
        wmma::load_matrix_sync(fA, Ah + (wm * 16) * APITCH + k, APITCH);
        #pragma unroll
        for (int j = 0; j < 4; ++j) {
            wmma::load_matrix_sync(fB, Bh + k * APITCH + wn * 64 + j * 16, APITCH);
            wmma::mma_sync(acc[j], fA, fB, acc[j]);
        }
    }

    __syncthreads();
    float* Cf = (float*)sm;
    #pragma unroll
    for (int j = 0; j < 4; ++j)
        wmma::store_matrix_sync(Cf + (wm * 16) * CPITCH + wn * 64 + j * 16,
                                acc[j], CPITCH, wmma::mem_row_major);
    __syncthreads();

    #pragma unroll
    for (int idx = tid; idx < 4096; idx += 512) {
        const int r  = idx >> 5;
        const int c4 = (idx & 31) * 4;
        const int gr = row0 + r;
        if (gr < M) {
            float4 v = *(const float4*)&Cf[r * CPITCH + c4];
            if (!isR) {
                const float4 bv = *(const float4*)&b1[c4];
                v.x += bv.x; v.y += bv.y; v.z += bv.z; v.w += bv.w;
            }
            __half2 h0 = __float22half2_rn(make_float2(v.x, v.y));
            __half2 h1 = __float22half2_rn(make_float2(v.z, v.w));
            uint2 o; o.x = *(unsigned*)&h0; o.y = *(unsigned*)&h1;
            *(uint2*)&C[(size_t)gr * HDIM + c4] = o;
        }
    }
}

// ---------------------------------------------------------------------------
// Counting sort by row.
// ---------------------------------------------------------------------------
__device__ __forceinline__ void load_idx(const void* eidx, int is64, int e,
                                         int E, int& row, int& col)
{
    if (is64) {
        const long long* p = (const long long*)eidx;
        row = (int)p[e];
        col = (int)p[(size_t)E + e];
    } else {
        const int* p = (const int*)eidx;
        row = p[e];
        col = p[(size_t)E + e];
    }
}

__global__ void zero_hist_kernel() {
    int i = blockIdx.x * blockDim.x + threadIdx.x;
    if (i < NBINS) g_hist[i] = 0;
}

__global__ void hist_kernel(const void* __restrict__ eidx, int E) {
    const int is64 = g_is64;
    for (int e = blockIdx.x * blockDim.x + threadIdx.x; e < E;
         e += gridDim.x * blockDim.x) {
        int row, col;
        load_idx(eidx, is64, e, E, row, col);
        atomicAdd(&g_hist[row], 1);
    }
}

// Stage A: per-block exclusive scan of 256 bins (coalesced), emit block sums.
__global__ __launch_bounds__(256)
void scan_a_kernel() {
    __shared__ int sh[256];
    const int t = threadIdx.x;
    const int i = blockIdx.x * 256 + t;
    const int v = g_hist[i];
    sh[t] = v;
    __syncthreads();
    #pragma unroll
    for (int off = 1; off < 256; off <<= 1) {
        int x = (t >= off) ? sh[t - off] : 0;
        __syncthreads();
        sh[t] += x;
        __syncthreads();
    }
    g_offs[i] = sh[t] - v;               // exclusive within block
    if (t == 255) g_bsum[blockIdx.x] = sh[255];
}

// Stage B: single-block exclusive scan of the 392 block sums.
__global__ __launch_bounds__(512, 1)
void scan_b_kernel() {
    __shared__ int sh[512];
    const int t = threadIdx.x;
    const int v = (t < NBLK_SCAN) ? g_bsum[t] : 0;
    sh[t] = v;
    __syncthreads();
    #pragma unroll
    for (int off = 1; off < 512; off <<= 1) {
        int x = (t >= off) ? sh[t - off] : 0;
        __syncthreads();
        sh[t] += x;
        __syncthreads();
    }
    if (t < NBLK_SCAN) g_bpre[t] = sh[t] - v;
}

// Stage C: add block prefixes back (coalesced).
__global__ __launch_bounds__(256)
void scan_c_kernel() {
    const int i = blockIdx.x * 256 + threadIdx.x;
    g_offs[i] += g_bpre[blockIdx.x];
}

__global__ void scatter_kernel(const void* __restrict__ eidx, int E) {
    const int is64 = g_is64;
    for (int e = blockIdx.x * blockDim.x + threadIdx.x; e < E;
         e += gridDim.x * blockDim.x) {
        int row, col;
        load_idx(eidx, is64, e, E, row, col);
        int pos = atomicAdd(&g_offs[row], 1);
        g_sorted[pos] = ((unsigned long long)row << 42)
                      | ((unsigned long long)col << 20)
                      | (unsigned)e;
    }
}

// ---------------------------------------------------------------------------
// Phase 2 (sorted): 4 edges/warp (8 lanes each) over the row-sorted list.
// ---------------------------------------------------------------------------
__device__ __forceinline__ float dot8h(uint4 u, uint4 r, float4 w0, float4 w1) {
    const __half2 z2 = __float2half2_rn(0.f);
    __half2 a0 = __hmax2(__hadd2(*(__half2*)&u.x, *(__half2*)&r.x), z2);
    __half2 a1 = __hmax2(__hadd2(*(__half2*)&u.y, *(__half2*)&r.y), z2);
    __half2 a2 = __hmax2(__hadd2(*(__half2*)&u.z, *(__half2*)&r.z), z2);
    __half2 a3 = __hmax2(__hadd2(*(__half2*)&u.w, *(__half2*)&r.w), z2);
    float2 f0 = __half22float2(a0);
    float2 f1 = __half22float2(a1);
    float2 f2 = __half22float2(a2);
    float2 f3 = __half22float2(a3);
    float s;
    s  = f0.x * w0.x;
    s  = fmaf(f0.y, w0.y, s);
    s  = fmaf(f1.x, w0.z, s);
    s  = fmaf(f1.y, w0.w, s);
    s  = fmaf(f2.x, w1.x, s);
    s  = fmaf(f2.y, w1.y, s);
    s  = fmaf(f3.x, w1.z, s);
    s  = fmaf(f3.y, w1.w, s);
    return s;
}

__global__ __launch_bounds__(256)
void edge_sorted_kernel(const float* __restrict__ W2,
                        const float* __restrict__ b2,
                        float* __restrict__ out,
                        int E)
{
    __shared__ float w2s[HDIM];
    const int tid = threadIdx.x;
    if (tid < HDIM) w2s[tid] = W2[tid];
    __syncthreads();

    const int warp = (blockIdx.x * 256 + tid) >> 5;
    const int lane = tid & 31;
    const int sub  = lane >> 3;
    const int l8   = lane & 7;
    const int i    = warp * 4 + sub;
    if (i >= E) return;

    const unsigned long long pk = g_sorted[i];
    const int row = (int)(pk >> 42);
    const int col = (int)((pk >> 20) & 0x3FFFFF);
    const int eid = (int)(pk & 0xFFFFF);

    const uint4* Up = (const uint4*)&g_U[(size_t)row * HDIM];
    const uint4* Rp = (const uint4*)&g_R[(size_t)col * HDIM];
    const uint4 ua = Up[l8],  ub = Up[l8 + 8];
    const uint4 ra = Rp[l8],  rb = Rp[l8 + 8];

    const float4* w4 = (const float4*)w2s;
    const float4 w0 = w4[2 * l8],      w1 = w4[2 * l8 + 1];
    const float4 w2 = w4[16 + 2 * l8], w3 = w4[16 + 2 * l8 + 1];

    float s = dot8h(ua, ra, w0, w1) + dot8h(ub, rb, w2, w3);

    const unsigned mask = 0xFFu << (sub * 8);
    #pragma unroll
    for (int off = 4; off; off >>= 1)
        s += __shfl_xor_sync(mask, s, off);

    if (l8 == 0) out[eid] = s + __ldg(b2);
}

// Fallback (unsorted) for out-of-range shapes.
__global__ __launch_bounds__(256)
void edge_kernel(const void* __restrict__ eidx,
                 const float* __restrict__ W2,
                 const float* __restrict__ b2,
                 float* __restrict__ out,
                 int E)
{
    __shared__ float w2s[HDIM];
    const int tid = threadIdx.x;
    if (tid < HDIM) w2s[tid] = W2[tid];
    __syncthreads();

    const int warp = (blockIdx.x * 256 + tid) >> 5;
    const int lane = tid & 31;
    const int sub  = lane >> 3;
    const int l8   = lane & 7;
    const int e    = warp * 4 + sub;
    if (e >= E) return;

    int row, col;
    load_idx(eidx, g_is64, e, E, row, col);

    const uint4* Up = (const uint4*)&g_U[(size_t)row * HDIM];
    const uint4* Rp = (const uint4*)&g_R[(size_t)col * HDIM];
    const uint4 ua = Up[l8],  ub = Up[l8 + 8];
    const uint4 ra = Rp[l8],  rb = Rp[l8 + 8];

    const float4* w4 = (const float4*)w2s;
    const float4 w0 = w4[2 * l8],      w1 = w4[2 * l8 + 1];
    const float4 w2 = w4[16 + 2 * l8], w3 = w4[16 + 2 * l8 + 1];

    float s = dot8h(ua, ra, w0, w1) + dot8h(ub, rb, w2, w3);

    const unsigned mask = 0xFFu << (sub * 8);
    #pragma unroll
    for (int off = 4; off; off >>= 1)
        s += __shfl_xor_sync(mask, s, off);

    if (l8 == 0) out[e] = s + __ldg(b2);
}

// ---------------------------------------------------------------------------
extern "C" void kernel_launch(void* const* d_in, const int* in_sizes, int n_in,
                              void* d_out, int out_size)
{
    const float* z_user   = (const float*)d_in[0];
    const float* z_recipe = (const float*)d_in[1];
    const void*  eidx     = d_in[2];
    const float* W1       = (const float*)d_in[3];
    const float* b1       = (const float*)d_in[4];
    const float* W2       = (const float*)d_in[5];
    const float* b2       = (const float*)d_in[6];
    float* out = (float*)d_out;

    const int Mu = in_sizes[0] / HDIM;
    const int Mr = in_sizes[1] / HDIM;
    const int E  = in_sizes[2] / 2;

    const int SMEM = 2 * TILEB;
    cudaFuncSetAttribute(precompute_kernel,
                         cudaFuncAttributeMaxDynamicSharedMemorySize, SMEM);

    const int gu = (Mu + 127) / 128;
    const int gr = (Mr + 127) / 128;
    precompute_kernel<<<gu + gr, 512, SMEM>>>(z_user, z_recipe, W1, b1,
                                              (const unsigned long long*)eidx,
                                              gu, Mu, Mr);

    const bool sortable = (E <= MAX_E) && (Mu <= NBINS) &&
                          (Mu < (1 << 22)) && (Mr < (1 << 22));
    if (sortable) {
        zero_hist_kernel<<<NBLK_SCAN, 256>>>();
        hist_kernel<<<1024, 256>>>(eidx, E);
        scan_a_kernel<<<NBLK_SCAN, 256>>>();
        scan_b_kernel<<<1, 512>>>();
        scan_c_kernel<<<NBLK_SCAN, 256>>>();
        scatter_kernel<<<1024, 256>>>(eidx, E);
        edge_sorted_kernel<<<(E + 31) / 32, 256>>>(W2, b2, out, E);
    } else {
        edge_kernel<<<(E + 31) / 32, 256>>>(eidx, W2, b2, out, E);
    }
}

// round 11
// speedup vs baseline: 1.6897x; 1.0053x over previous
#include <cuda_runtime.h>
#include <cuda_fp16.h>
#include <mma.h>

using namespace nvcuda;

// ---------------------------------------------------------------------------
// EdgeDecoder: out[e] = relu([zu[row]; zr[col]] @ W1 + b1) @ W2 + b2
// U = zu @ W1_top + b1 ; R = zr @ W1_bot  (fp16 HMMA, fp32 acc; at the
// 256-MAC/cyc/SM tensor floor). U,R stored fp16.
// R11: sort chain (depends only on eidx) forked onto a second stream and
//      overlapped with precompute; zero_hist folded into scan_c (zero-
//      restore invariant); is64 detected per-block inside hist/scatter.
// ---------------------------------------------------------------------------

#define HDIM 128
#define MAX_USER   100000
#define MAX_RECIPE 50000
#define MAX_E      (1 << 20)
#define NBLK_SCAN  392
#define NBINS      (NBLK_SCAN * 256)   // 100352 >= MAX_USER

__device__ __half g_U[(size_t)MAX_USER * HDIM];
__device__ __half g_R[(size_t)MAX_RECIPE * HDIM];
__device__ int    g_is64;
__device__ int    g_hist[NBINS];       // invariant: all-zero at kernel entry
__device__ int    g_offs[NBINS];
__device__ int    g_bsum[NBLK_SCAN];
__device__ int    g_bpre[NBLK_SCAN];
__device__ unsigned long long g_sorted[MAX_E];   // row:22 | col:22 | eid:20

#define APITCH 136
#define TILEB  (128 * APITCH * 2)
#define CPITCH 132

// ---------------------------------------------------------------------------
// Phase 1: fp16 HMMA precompute (unchanged). Sets g_is64 (fallback path).
// ---------------------------------------------------------------------------
__global__ __launch_bounds__(512, 2)
void precompute_kernel(const float* __restrict__ Zu,
                       const float* __restrict__ Zr,
                       const float* __restrict__ W1,
                       const float* __restrict__ b1,
                       const unsigned long long* __restrict__ eidx,
                       int gu, int Mu, int Mr)
{
    extern __shared__ __align__(16) char sm[];
    __half* Ah = (__half*)sm;
    __half* Bh = (__half*)(sm + TILEB);

    if (blockIdx.x == 0 && threadIdx.x == 0) {
        int is64 = 1;
        #pragma unroll
        for (int i = 0; i < 32; ++i)
            if ((eidx[i] >> 32) != 0ull) is64 = 0;
        g_is64 = is64;
    }

    const bool isR = (blockIdx.x >= (unsigned)gu);
    const int  blk = isR ? (blockIdx.x - gu) : blockIdx.x;
    const int  M   = isR ? Mr : Mu;
    const float* __restrict__ Z  = isR ? Zr : Zu;
    const float* __restrict__ Wp = isR ? (W1 + HDIM * HDIM) : W1;
    __half* __restrict__ C       = isR ? g_R : g_U;

    const int tid  = threadIdx.x;
    const int row0 = blk * 128;

    #pragma unroll
    for (int idx = tid; idx < 4096; idx += 512) {
        const int r  = idx >> 5;
        const int c4 = (idx & 31) * 4;
        float4 v = ((const float4*)Wp)[idx];
        __half2 p0 = __float22half2_rn(make_float2(v.x, v.y));
        __half2 p1 = __float22half2_rn(make_float2(v.z, v.w));
        uint2 hh; hh.x = *(unsigned*)&p0; hh.y = *(unsigned*)&p1;
        *(uint2*)&Bh[r * APITCH + c4] = hh;
    }
    #pragma unroll
    for (int idx = tid; idx < 4096; idx += 512) {
        const int r  = idx >> 5;
        const int c4 = (idx & 31) * 4;
        const int gr = row0 + r;
        float4 v = make_float4(0.f, 0.f, 0.f, 0.f);
        if (gr < M) v = ((const float4*)Z)[(size_t)gr * 32 + (idx & 31)];
        __half2 p0 = __float22half2_rn(make_float2(v.x, v.y));
        __half2 p1 = __float22half2_rn(make_float2(v.z, v.w));
        uint2 hh; hh.x = *(unsigned*)&p0; hh.y = *(unsigned*)&p1;
        *(uint2*)&Ah[r * APITCH + c4] = hh;
    }
    __syncthreads();

    const int warp = tid >> 5;
    const int wm   = warp >> 1;
    const int wn   = warp & 1;

    wmma::fragment<wmma::accumulator, 16, 16, 16, float> acc[4];
    #pragma unroll
    for (int j = 0; j < 4; ++j) wmma::fill_fragment(acc[j], 0.f);

    wmma::fragment<wmma::matrix_a, 16, 16, 16, __half, wmma::row_major> fA;
    wmma::fragment<wmma::matrix_b, 16, 16, 16, __half, wmma::row_major> fB;

    #pragma unroll
    for (int k = 0; k < HDIM; k += 16) {
        wmma::load_matrix_sync(fA, Ah + (wm * 16) * APITCH + k, APITCH);
        #pragma unroll
        for (int j = 0; j < 4; ++j) {
            wmma::load_matrix_sync(fB, Bh + k * APITCH + wn * 64 + j * 16, APITCH);
            wmma::mma_sync(acc[j], fA, fB, acc[j]);
        }
    }

    __syncthreads();
    float* Cf = (float*)sm;
    #pragma unroll
    for (int j = 0; j < 4; ++j)
        wmma::store_matrix_sync(Cf + (wm * 16) * CPITCH + wn * 64 + j * 16,
                                acc[j], CPITCH, wmma::mem_row_major);
    __syncthreads();

    #pragma unroll
    for (int idx = tid; idx < 4096; idx += 512) {
        const int r  = idx >> 5;
        const int c4 = (idx & 31) * 4;
        const int gr = row0 + r;
        if (gr < M) {
            float4 v = *(const float4*)&Cf[r * CPITCH + c4];
            if (!isR) {
                const float4 bv = *(const float4*)&b1[c4];
                v.x += bv.x; v.y += bv.y; v.z += bv.z; v.w += bv.w;
            }
            __half2 h0 = __float22half2_rn(make_float2(v.x, v.y));
            __half2 h1 = __float22half2_rn(make_float2(v.z, v.w));
            uint2 o; o.x = *(unsigned*)&h0; o.y = *(unsigned*)&h1;
            *(uint2*)&C[(size_t)gr * HDIM + c4] = o;
        }
    }
}

// ---------------------------------------------------------------------------
// Counting sort by row (independent of precompute: detects is64 per block).
// ---------------------------------------------------------------------------
__device__ __forceinline__ int detect_is64_block(const unsigned long long* p) {
    __shared__ int s_is64;
    if (threadIdx.x == 0) {
        int v = 1;
        #pragma unroll
        for (int i = 0; i < 32; ++i)
            if ((p[i] >> 32) != 0ull) v = 0;
        s_is64 = v;
    }
    __syncthreads();
    return s_is64;
}

__device__ __forceinline__ void load_idx(const void* eidx, int is64, int e,
                                         int E, int& row, int& col)
{
    if (is64) {
        const long long* p = (const long long*)eidx;
        row = (int)p[e];
        col = (int)p[(size_t)E + e];
    } else {
        const int* p = (const int*)eidx;
        row = p[e];
        col = p[(size_t)E + e];
    }
}

__global__ void hist_kernel(const void* __restrict__ eidx, int E) {
    const int is64 = detect_is64_block((const unsigned long long*)eidx);
    for (int e = blockIdx.x * blockDim.x + threadIdx.x; e < E;
         e += gridDim.x * blockDim.x) {
        int row, col;
        load_idx(eidx, is64, e, E, row, col);
        atomicAdd(&g_hist[row], 1);
    }
}

__global__ __launch_bounds__(256)
void scan_a_kernel() {
    __shared__ int sh[256];
    const int t = threadIdx.x;
    const int i = blockIdx.x * 256 + t;
    const int v = g_hist[i];
    sh[t] = v;
    __syncthreads();
    #pragma unroll
    for (int off = 1; off < 256; off <<= 1) {
        int x = (t >= off) ? sh[t - off] : 0;
        __syncthreads();
        sh[t] += x;
        __syncthreads();
    }
    g_offs[i] = sh[t] - v;
    if (t == 255) g_bsum[blockIdx.x] = sh[255];
}

__global__ __launch_bounds__(512, 1)
void scan_b_kernel() {
    __shared__ int sh[512];
    const int t = threadIdx.x;
    const int v = (t < NBLK_SCAN) ? g_bsum[t] : 0;
    sh[t] = v;
    __syncthreads();
    #pragma unroll
    for (int off = 1; off < 512; off <<= 1) {
        int x = (t >= off) ? sh[t - off] : 0;
        __syncthreads();
        sh[t] += x;
        __syncthreads();
    }
    if (t < NBLK_SCAN) g_bpre[t] = sh[t] - v;
}

// Stage C: add block prefixes AND restore g_hist zero-invariant for replay.
__global__ __launch_bounds__(256)
void scan_c_kernel() {
    const int i = blockIdx.x * 256 + threadIdx.x;
    g_offs[i] += g_bpre[blockIdx.x];
    g_hist[i] = 0;
}

__global__ void scatter_kernel(const void* __restrict__ eidx, int E) {
    const int is64 = detect_is64_block((const unsigned long long*)eidx);
    for (int e = blockIdx.x * blockDim.x + threadIdx.x; e < E;
         e += gridDim.x * blockDim.x) {
        int row, col;
        load_idx(eidx, is64, e, E, row, col);
        int pos = atomicAdd(&g_offs[row], 1);
        g_sorted[pos] = ((unsigned long long)row << 42)
                      | ((unsigned long long)col << 20)
                      | (unsigned)e;
    }
}

// ---------------------------------------------------------------------------
// Phase 2 (sorted): 4 edges/warp (8 lanes each) over the row-sorted list.
// ---------------------------------------------------------------------------
__device__ __forceinline__ float dot8h(uint4 u, uint4 r, float4 w0, float4 w1) {
    const __half2 z2 = __float2half2_rn(0.f);
    __half2 a0 = __hmax2(__hadd2(*(__half2*)&u.x, *(__half2*)&r.x), z2);
    __half2 a1 = __hmax2(__hadd2(*(__half2*)&u.y, *(__half2*)&r.y), z2);
    __half2 a2 = __hmax2(__hadd2(*(__half2*)&u.z, *(__half2*)&r.z), z2);
    __half2 a3 = __hmax2(__hadd2(*(__half2*)&u.w, *(__half2*)&r.w), z2);
    float2 f0 = __half22float2(a0);
    float2 f1 = __half22float2(a1);
    float2 f2 = __half22float2(a2);
    float2 f3 = __half22float2(a3);
    float s;
    s  = f0.x * w0.x;
    s  = fmaf(f0.y, w0.y, s);
    s  = fmaf(f1.x, w0.z, s);
    s  = fmaf(f1.y, w0.w, s);
    s  = fmaf(f2.x, w1.x, s);
    s  = fmaf(f2.y, w1.y, s);
    s  = fmaf(f3.x, w1.z, s);
    s  = fmaf(f3.y, w1.w, s);
    return s;
}

__global__ __launch_bounds__(256)
void edge_sorted_kernel(const float* __restrict__ W2,
                        const float* __restrict__ b2,
                        float* __restrict__ out,
                        int E)
{
    __shared__ float w2s[HDIM];
    const int tid = threadIdx.x;
    if (tid < HDIM) w2s[tid] = W2[tid];
    __syncthreads();

    const int warp = (blockIdx.x * 256 + tid) >> 5;
    const int lane = tid & 31;
    const int sub  = lane >> 3;
    const int l8   = lane & 7;
    const int i    = warp * 4 + sub;
    if (i >= E) return;

    const unsigned long long pk = g_sorted[i];
    const int row = (int)(pk >> 42);
    const int col = (int)((pk >> 20) & 0x3FFFFF);
    const int eid = (int)(pk & 0xFFFFF);

    const uint4* Up = (const uint4*)&g_U[(size_t)row * HDIM];
    const uint4* Rp = (const uint4*)&g_R[(size_t)col * HDIM];
    const uint4 ua = Up[l8],  ub = Up[l8 + 8];
    const uint4 ra = Rp[l8],  rb = Rp[l8 + 8];

    const float4* w4 = (const float4*)w2s;
    const float4 w0 = w4[2 * l8],      w1 = w4[2 * l8 + 1];
    const float4 w2 = w4[16 + 2 * l8], w3 = w4[16 + 2 * l8 + 1];

    float s = dot8h(ua, ra, w0, w1) + dot8h(ub, rb, w2, w3);

    const unsigned mask = 0xFFu << (sub * 8);
    #pragma unroll
    for (int off = 4; off; off >>= 1)
        s += __shfl_xor_sync(mask, s, off);

    if (l8 == 0) out[eid] = s + __ldg(b2);
}

// Fallback (unsorted) for out-of-range shapes.
__global__ __launch_bounds__(256)
void edge_kernel(const void* __restrict__ eidx,
                 const float* __restrict__ W2,
                 const float* __restrict__ b2,
                 float* __restrict__ out,
                 int E)
{
    __shared__ float w2s[HDIM];
    const int tid = threadIdx.x;
    if (tid < HDIM) w2s[tid] = W2[tid];
    __syncthreads();

    const int warp = (blockIdx.x * 256 + tid) >> 5;
    const int lane = tid & 31;
    const int sub  = lane >> 3;
    const int l8   = lane & 7;
    const int e    = warp * 4 + sub;
    if (e >= E) return;

    int row, col;
    load_idx(eidx, g_is64, e, E, row, col);

    const uint4* Up = (const uint4*)&g_U[(size_t)row * HDIM];
    const uint4* Rp = (const uint4*)&g_R[(size_t)col * HDIM];
    const uint4 ua = Up[l8],  ub = Up[l8 + 8];
    const uint4 ra = Rp[l8],  rb = Rp[l8 + 8];

    const float4* w4 = (const float4*)w2s;
    const float4 w0 = w4[2 * l8],      w1 = w4[2 * l8 + 1];
    const float4 w2 = w4[16 + 2 * l8], w3 = w4[16 + 2 * l8 + 1];

    float s = dot8h(ua, ra, w0, w1) + dot8h(ub, rb, w2, w3);

    const unsigned mask = 0xFFu << (sub * 8);
    #pragma unroll
    for (int off = 4; off; off >>= 1)
        s += __shfl_xor_sync(mask, s, off);

    if (l8 == 0) out[e] = s + __ldg(b2);
}

// ---------------------------------------------------------------------------
// kernel_launch: fork sort chain (eidx-only) onto a side stream, overlap with
// precompute, join before edge_sorted. Stream/events are process-lifetime
// host objects (no device allocation); identical work recorded every call.
// ---------------------------------------------------------------------------
extern "C" void kernel_launch(void* const* d_in, const int* in_sizes, int n_in,
                              void* d_out, int out_size)
{
    const float* z_user   = (const float*)d_in[0];
    const float* z_recipe = (const float*)d_in[1];
    const void*  eidx     = d_in[2];
    const float* W1       = (const float*)d_in[3];
    const float* b1       = (const float*)d_in[4];
    const float* W2       = (const float*)d_in[5];
    const float* b2       = (const float*)d_in[6];
    float* out = (float*)d_out;

    const int Mu = in_sizes[0] / HDIM;
    const int Mr = in_sizes[1] / HDIM;
    const int E  = in_sizes[2] / 2;

    const int SMEM = 2 * TILEB;
    cudaFuncSetAttribute(precompute_kernel,
                         cudaFuncAttributeMaxDynamicSharedMemorySize, SMEM);

    const int gu = (Mu + 127) / 128;
    const int gr = (Mr + 127) / 128;

    const bool sortable = (E <= MAX_E) && (E >= 64) && (Mu <= NBINS) &&
                          (Mu < (1 << 22)) && (Mr < (1 << 22));

    if (sortable) {
        static cudaStream_t s1 = []() {
            cudaStream_t s;
            cudaStreamCreateWithFlags(&s, cudaStreamNonBlocking);
            return s;
        }();
        static cudaEvent_t evFork = []() {
            cudaEvent_t e;
            cudaEventCreateWithFlags(&e, cudaEventDisableTiming);
            return e;
        }();
        static cudaEvent_t evJoin = []() {
            cudaEvent_t e;
            cudaEventCreateWithFlags(&e, cudaEventDisableTiming);
            return e;
        }();

        // Fork: sort chain depends only on eidx.
        cudaEventRecord(evFork, 0);
        cudaStreamWaitEvent(s1, evFork, 0);

        precompute_kernel<<<gu + gr, 512, SMEM>>>(z_user, z_recipe, W1, b1,
                                                  (const unsigned long long*)eidx,
                                                  gu, Mu, Mr);

        hist_kernel<<<1024, 256, 0, s1>>>(eidx, E);
        scan_a_kernel<<<NBLK_SCAN, 256, 0, s1>>>();
        scan_b_kernel<<<1, 512, 0, s1>>>();
        scan_c_kernel<<<NBLK_SCAN, 256, 0, s1>>>();
        scatter_kernel<<<1024, 256, 0, s1>>>(eidx, E);

        // Join: edge_sorted needs U,R (stream 0) and g_sorted (s1).
        cudaEventRecord(evJoin, s1);
        cudaStreamWaitEvent(0, evJoin, 0);

        edge_sorted_kernel<<<(E + 31) / 32, 256>>>(W2, b2, out, E);
    } else {
        precompute_kernel<<<gu + gr, 512, SMEM>>>(z_user, z_recipe, W1, b1,
                                                  (const unsigned long long*)eidx,
                                                  gu, Mu, Mr);
        edge_kernel<<<(E + 31) / 32, 256>>>(eidx, W2, b2, out, E);
    }
}

// round 12
// speedup vs baseline: 2.3513x; 1.3916x over previous
#include <cuda_runtime.h>
#include <cuda_fp16.h>
#include <mma.h>

using namespace nvcuda;

// ---------------------------------------------------------------------------
// EdgeDecoder: out[e] = relu([zu[row]; zr[col]] @ W1 + b1) @ W2 + b2
// U = zu @ W1_top + b1 ; R = zr @ W1_bot  (fp16 HMMA, fp32 acc). U,R fp16.
// R12: sort chain reverted (negative-sum in L2 random ops). New: runtime
//      max-row detection -> U tiles beyond the used row range exit early
//      (reference draws rows from [0,50K) but z_user has 100K rows; half
//      the U GEMM was dead work). g_maxrow accumulates via atomicMax and is
//      idempotent across graph replays (same input -> same max).
// ---------------------------------------------------------------------------

#define HDIM 128
#define MAX_USER   100000
#define MAX_RECIPE 50000

__device__ __half g_U[(size_t)MAX_USER * HDIM];    // 25.6 MB
__device__ __half g_R[(size_t)MAX_RECIPE * HDIM];  // 12.8 MB
__device__ int    g_is64;
__device__ int    g_maxrow;          // zero-init; atomicMax, idempotent

#define APITCH 136
#define TILEB  (128 * APITCH * 2)
#define CPITCH 132

// ---------------------------------------------------------------------------
// Per-block index-dtype sniff (int64 vs int32-viewed-as-pairs; values are
// small, so genuine int64 data has zero high words on the first 32 entries).
// ---------------------------------------------------------------------------
__device__ __forceinline__ int detect_is64_block(const unsigned long long* p) {
    __shared__ int s_is64;
    if (threadIdx.x == 0) {
        int v = 1;
        #pragma unroll
        for (int i = 0; i < 32; ++i)
            if ((p[i] >> 32) != 0ull) v = 0;
        s_is64 = v;
    }
    __syncthreads();
    return s_is64;
}

// ---------------------------------------------------------------------------
// Max row-index reduction (rows = first E entries of eidx).
// ---------------------------------------------------------------------------
__global__ __launch_bounds__(256)
void maxrow_kernel(const void* __restrict__ eidx, int E)
{
    const int is64 = detect_is64_block((const unsigned long long*)eidx);
    int m = 0;
    for (int e = blockIdx.x * blockDim.x + threadIdx.x; e < E;
         e += gridDim.x * blockDim.x) {
        int row = is64 ? (int)((const long long*)eidx)[e]
                       : ((const int*)eidx)[e];
        m = max(m, row);
    }
    #pragma unroll
    for (int off = 16; off; off >>= 1)
        m = max(m, __shfl_xor_sync(0xffffffffu, m, off));
    if ((threadIdx.x & 31) == 0) atomicMax(&g_maxrow, m);
}

// ---------------------------------------------------------------------------
// Phase 1: fp16 HMMA precompute. U tiles beyond g_maxrow exit immediately.
// ---------------------------------------------------------------------------
__global__ __launch_bounds__(512, 2)
void precompute_kernel(const float* __restrict__ Zu,
                       const float* __restrict__ Zr,
                       const float* __restrict__ W1,
                       const float* __restrict__ b1,
                       const unsigned long long* __restrict__ eidx,
                       int gu, int Mu, int Mr)
{
    extern __shared__ __align__(16) char sm[];
    __half* Ah = (__half*)sm;
    __half* Bh = (__half*)(sm + TILEB);

    if (blockIdx.x == 0 && threadIdx.x == 0) {
        int is64 = 1;
        #pragma unroll
        for (int i = 0; i < 32; ++i)
            if ((eidx[i] >> 32) != 0ull) is64 = 0;
        g_is64 = is64;
    }

    const bool isR = (blockIdx.x >= (unsigned)gu);
    const int  blk = isR ? (blockIdx.x - gu) : blockIdx.x;
    const int  row0 = blk * 128;

    // Early-exit: U rows above the maximum referenced row are never read.
    if (!isR && row0 > g_maxrow) return;

    const int  M   = isR ? Mr : Mu;
    const float* __restrict__ Z  = isR ? Zr : Zu;
    const float* __restrict__ Wp = isR ? (W1 + HDIM * HDIM) : W1;
    __half* __restrict__ C       = isR ? g_R : g_U;

    const int tid = threadIdx.x;

    #pragma unroll
    for (int idx = tid; idx < 4096; idx += 512) {
        const int r  = idx >> 5;
        const int c4 = (idx & 31) * 4;
        float4 v = ((const float4*)Wp)[idx];
        __half2 p0 = __float22half2_rn(make_float2(v.x, v.y));
        __half2 p1 = __float22half2_rn(make_float2(v.z, v.w));
        uint2 hh; hh.x = *(unsigned*)&p0; hh.y = *(unsigned*)&p1;
        *(uint2*)&Bh[r * APITCH + c4] = hh;
    }
    #pragma unroll
    for (int idx = tid; idx < 4096; idx += 512) {
        const int r  = idx >> 5;
        const int c4 = (idx & 31) * 4;
        const int gr = row0 + r;
        float4 v = make_float4(0.f, 0.f, 0.f, 0.f);
        if (gr < M) v = ((const float4*)Z)[(size_t)gr * 32 + (idx & 31)];
        __half2 p0 = __float22half2_rn(make_float2(v.x, v.y));
        __half2 p1 = __float22half2_rn(make_float2(v.z, v.w));
        uint2 hh; hh.x = *(unsigned*)&p0; hh.y = *(unsigned*)&p1;
        *(uint2*)&Ah[r * APITCH + c4] = hh;
    }
    __syncthreads();

    const int warp = tid >> 5;
    const int wm   = warp >> 1;
    const int wn   = warp & 1;

    wmma::fragment<wmma::accumulator, 16, 16, 16, float> acc[4];
    #pragma unroll
    for (int j = 0; j < 4; ++j) wmma::fill_fragment(acc[j], 0.f);

    wmma::fragment<wmma::matrix_a, 16, 16, 16, __half, wmma::row_major> fA;
    wmma::fragment<wmma::matrix_b, 16, 16, 16, __half, wmma::row_major> fB;

    #pragma unroll
    for (int k = 0; k < HDIM; k += 16) {
        wmma::load_matrix_sync(fA, Ah + (wm * 16) * APITCH + k, APITCH);
        #pragma unroll
        for (int j = 0; j < 4; ++j) {
            wmma::load_matrix_sync(fB, Bh + k * APITCH + wn * 64 + j * 16, APITCH);
            wmma::mma_sync(acc[j], fA, fB, acc[j]);
        }
    }

    __syncthreads();
    float* Cf = (float*)sm;
    #pragma unroll
    for (int j = 0; j < 4; ++j)
        wmma::store_matrix_sync(Cf + (wm * 16) * CPITCH + wn * 64 + j * 16,
                                acc[j], CPITCH, wmma::mem_row_major);
    __syncthreads();

    #pragma unroll
    for (int idx = tid; idx < 4096; idx += 512) {
        const int r  = idx >> 5;
        const int c4 = (idx & 31) * 4;
        const int gr = row0 + r;
        if (gr < M) {
            float4 v = *(const float4*)&Cf[r * CPITCH + c4];
            if (!isR) {
                const float4 bv = *(const float4*)&b1[c4];
                v.x += bv.x; v.y += bv.y; v.z += bv.z; v.w += bv.w;
            }
            __half2 h0 = __float22half2_rn(make_float2(v.x, v.y));
            __half2 h1 = __float22half2_rn(make_float2(v.z, v.w));
            uint2 o; o.x = *(unsigned*)&h0; o.y = *(unsigned*)&h1;
            *(uint2*)&C[(size_t)gr * HDIM + c4] = o;
        }
    }
}

// ---------------------------------------------------------------------------
// Phase 2: four edges per warp (8 lanes each). Lane l8 loads chunk l8 and
// l8+8: each 8-lane LDG.128 group covers one full 128B line.
// ---------------------------------------------------------------------------
__device__ __forceinline__ float dot8h(uint4 u, uint4 r, float4 w0, float4 w1) {
    const __half2 z2 = __float2half2_rn(0.f);
    __half2 a0 = __hmax2(__hadd2(*(__half2*)&u.x, *(__half2*)&r.x), z2);
    __half2 a1 = __hmax2(__hadd2(*(__half2*)&u.y, *(__half2*)&r.y), z2);
    __half2 a2 = __hmax2(__hadd2(*(__half2*)&u.z, *(__half2*)&r.z), z2);
    __half2 a3 = __hmax2(__hadd2(*(__half2*)&u.w, *(__half2*)&r.w), z2);
    float2 f0 = __half22float2(a0);
    float2 f1 = __half22float2(a1);
    float2 f2 = __half22float2(a2);
    float2 f3 = __half22float2(a3);
    float s;
    s  = f0.x * w0.x;
    s  = fmaf(f0.y, w0.y, s);
    s  = fmaf(f1.x, w0.z, s);
    s  = fmaf(f1.y, w0.w, s);
    s  = fmaf(f2.x, w1.x, s);
    s  = fmaf(f2.y, w1.y, s);
    s  = fmaf(f3.x, w1.z, s);
    s  = fmaf(f3.y, w1.w, s);
    return s;
}

__global__ __launch_bounds__(256)
void edge_kernel(const void* __restrict__ eidx,
                 const float* __restrict__ W2,
                 const float* __restrict__ b2,
                 float* __restrict__ out,
                 int E)
{
    __shared__ float w2s[HDIM];
    const int tid = threadIdx.x;
    if (tid < HDIM) w2s[tid] = W2[tid];
    __syncthreads();

    const int warp = (blockIdx.x * 256 + tid) >> 5;
    const int lane = tid & 31;
    const int sub  = lane >> 3;
    const int l8   = lane & 7;
    const int e    = warp * 4 + sub;
    if (e >= E) return;

    int row, col;
    if (g_is64) {
        const long long* p = (const long long*)eidx;
        row = (int)p[e];
        col = (int)p[(size_t)E + e];
    } else {
        const int* p = (const int*)eidx;
        row = p[e];
        col = p[(size_t)E + e];
    }

    const uint4* Up = (const uint4*)&g_U[(size_t)row * HDIM];
    const uint4* Rp = (const uint4*)&g_R[(size_t)col * HDIM];
    const uint4 ua = Up[l8],  ub = Up[l8 + 8];
    const uint4 ra = Rp[l8],  rb = Rp[l8 + 8];

    const float4* w4 = (const float4*)w2s;
    const float4 w0 = w4[2 * l8],      w1 = w4[2 * l8 + 1];
    const float4 w2 = w4[16 + 2 * l8], w3 = w4[16 + 2 * l8 + 1];

    float s = dot8h(ua, ra, w0, w1) + dot8h(ub, rb, w2, w3);

    const unsigned mask = 0xFFu << (sub * 8);
    #pragma unroll
    for (int off = 4; off; off >>= 1)
        s += __shfl_xor_sync(mask, s, off);

    if (l8 == 0) out[e] = s + __ldg(b2);
}

// ---------------------------------------------------------------------------
extern "C" void kernel_launch(void* const* d_in, const int* in_sizes, int n_in,
                              void* d_out, int out_size)
{
    const float* z_user   = (const float*)d_in[0];
    const float* z_recipe = (const float*)d_in[1];
    const void*  eidx     = d_in[2];
    const float* W1       = (const float*)d_in[3];
    const float* b1       = (const float*)d_in[4];
    const float* W2       = (const float*)d_in[5];
    const float* b2       = (const float*)d_in[6];
    float* out = (float*)d_out;

    const int Mu = in_sizes[0] / HDIM;
    const int Mr = in_sizes[1] / HDIM;
    const int E  = in_sizes[2] / 2;

    const int SMEM = 2 * TILEB;
    cudaFuncSetAttribute(precompute_kernel,
                         cudaFuncAttributeMaxDynamicSharedMemorySize, SMEM);

    const int gu = (Mu + 127) / 128;
    const int gr = (Mr + 127) / 128;

    maxrow_kernel<<<256, 256>>>(eidx, E);
    precompute_kernel<<<gu + gr, 512, SMEM>>>(z_user, z_recipe, W1, b1,
                                              (const unsigned long long*)eidx,
                                              gu, Mu, Mr);
    edge_kernel<<<(E + 31) / 32, 256>>>(eidx, W2, b2, out, E);
}